// round 10
// baseline (speedup 1.0000x reference)
#include <cuda_runtime.h>
#include <math.h>

// Problem constants
#define NSAMP 4096
#define GD    2016
#define LDF   65     // sA leading dim (scalar, conflict-free both row & col)
#define LDFV  68     // buildA tiles leading dim (float4-aligned, conflict-free)

// Output layout: recons [4096,64], pred [4096,2], latent [4096,64]
#define REC_OFF  0
#define PRED_OFF (NSAMP * 64)
#define LAT_OFF  (NSAMP * 64 + NSAMP * 2)

__device__ float g_vec[(size_t)NSAMP * GD];   // packed gi @ W_up^T + b_up
__device__ float g_Wt[5 * 4096];              // transposed W1..W5
__device__ unsigned int g_rc[GD];             // packed smem offsets: lo=r*LDF+c, hi=c*LDF+r

#define FULLM 0xffffffffu

__device__ __forceinline__ float frcp(float x) {
    float r; asm("rcp.approx.f32 %0, %1;" : "=f"(r) : "f"(x)); return r;
}

// ---------------------------------------------------------------------------
// Kernel 1: GEMM [4096,64] x [64,2016]^T -> packed g_vec. float4 smem loads.
// ---------------------------------------------------------------------------
__global__ __launch_bounds__(256) void k_buildA(
    const float* __restrict__ gi,
    const float* __restrict__ Wup,
    const float* __restrict__ bup)
{
    __shared__ float sG[64 * LDFV];
    __shared__ float sW[64 * LDFV];

    const int tid  = threadIdx.x;
    const int pIdx = blockIdx.x * 64;
    const int sIdx = blockIdx.y * 64;

    for (int lin = tid; lin < 4096; lin += 256) {
        int row = lin >> 6, k = lin & 63;
        sG[row * LDFV + k] = gi[(sIdx + row) * 64 + k];
        int p = pIdx + row;
        sW[row * LDFV + k] = (p < GD) ? Wup[p * 64 + k] : 0.0f;
    }
    __syncthreads();

    const int cg = tid & 15;
    const int rg = tid >> 4;

    float acc[4][4];
#pragma unroll
    for (int a = 0; a < 4; ++a)
#pragma unroll
        for (int b = 0; b < 4; ++b) acc[a][b] = 0.0f;

#pragma unroll
    for (int k = 0; k < 64; k += 4) {
        float4 Av[4], Bv[4];
#pragma unroll
        for (int a = 0; a < 4; ++a)
            Av[a] = *(const float4*)&sG[(rg + 16 * a) * LDFV + k];
#pragma unroll
        for (int b = 0; b < 4; ++b)
            Bv[b] = *(const float4*)&sW[(cg + 16 * b) * LDFV + k];
#pragma unroll
        for (int a = 0; a < 4; ++a)
#pragma unroll
            for (int b = 0; b < 4; ++b) {
                acc[a][b] = fmaf(Av[a].x, Bv[b].x, acc[a][b]);
                acc[a][b] = fmaf(Av[a].y, Bv[b].y, acc[a][b]);
                acc[a][b] = fmaf(Av[a].z, Bv[b].z, acc[a][b]);
                acc[a][b] = fmaf(Av[a].w, Bv[b].w, acc[a][b]);
            }
    }

#pragma unroll
    for (int b = 0; b < 4; ++b) {
        int p = pIdx + cg + 16 * b;
        if (p >= GD) continue;
        float bb = bup[p];
#pragma unroll
        for (int a = 0; a < 4; ++a) {
            int s = sIdx + rg + 16 * a;
            g_vec[(size_t)s * GD + p] = acc[a][b] + bb;
        }
    }
}

// ---------------------------------------------------------------------------
// Prep: transpose W1..W5 into g_Wt, and build (r,c)->smem-offset LUT
// ---------------------------------------------------------------------------
__global__ __launch_bounds__(256) void k_prep(
    const float* __restrict__ W1, const float* __restrict__ W2,
    const float* __restrict__ W3, const float* __restrict__ W4,
    const float* __restrict__ W5)
{
    int idx = blockIdx.x * 256 + threadIdx.x;
    if (idx < 5 * 4096) {
        int m = idx >> 12;
        int r = idx & 4095;
        int i = r >> 6, j = r & 63;
        const float* W = (m == 0) ? W1 : (m == 1) ? W2 : (m == 2) ? W3 : (m == 3) ? W4 : W5;
        g_Wt[m * 4096 + j * 64 + i] = W[i * 64 + j];
    } else if (idx < 5 * 4096 + GD) {
        int p = idx - 5 * 4096;
        float t = sqrtf(8.0f * (float)p + 1.0f);
        int r = (int)((1.0f + t) * 0.5f);
        while (r * (r - 1) / 2 > p) --r;
        while ((r + 1) * r / 2 <= p) ++r;
        int c = p - r * (r - 1) / 2;
        g_rc[p] = (unsigned int)(r * LDF + c) | ((unsigned int)(c * LDF + r) << 16);
    }
}

// ---------------------------------------------------------------------------
// Warp primitives. Lane owns rows (lane) -> r0[], (lane+32) -> r1[].
// ---------------------------------------------------------------------------
__device__ __forceinline__ void lu64(float (&r0)[64], float (&r1)[64],
                                     float& dinv0, float& dinv1, int lane)
{
#pragma unroll
    for (int k = 0; k < 63; ++k) {
        if (k < 32) {
            float piv  = __shfl_sync(FULLM, r0[k], k);
            float pinv = frcp(piv);
            dinv0 = (lane == k) ? pinv : dinv0;
            float l0 = (lane > k) ? r0[k] * pinv : 0.0f;
            r0[k] = (lane > k) ? l0 : r0[k];
            float l1 = r1[k] * pinv;
            r1[k] = l1;
#pragma unroll
            for (int j = k + 1; j < 64; ++j) {
                float bj = __shfl_sync(FULLM, r0[j], k);
                r0[j] = fmaf(-l0, bj, r0[j]);
                r1[j] = fmaf(-l1, bj, r1[j]);
            }
        } else {
            float piv  = __shfl_sync(FULLM, r1[k], k - 32);
            float pinv = frcp(piv);
            dinv1 = (lane == k - 32) ? pinv : dinv1;
            float l1 = (lane > k - 32) ? r1[k] * pinv : 0.0f;
            r1[k] = (lane > k - 32) ? l1 : r1[k];
#pragma unroll
            for (int j = k + 1; j < 64; ++j) {
                float bj = __shfl_sync(FULLM, r1[j], k - 32);
                r1[j] = fmaf(-l1, bj, r1[j]);
            }
        }
    }
    {
        float piv  = __shfl_sync(FULLM, r1[63], 31);
        float pinv = frcp(piv);
        dinv1 = (lane == 31) ? pinv : dinv1;
    }
}

// Solve (LU) x = b with ROW-distributed factors.
__device__ __forceinline__ void solve64(const float (&r0)[64], const float (&r1)[64],
                                        float dinv0, float dinv1, int lane,
                                        float b0, float b1, float& x0, float& x1)
{
    float a0 = b0, a1 = b1;
#pragma unroll
    for (int k = 0; k < 64; ++k) {
        if (k < 32) {
            float zk = __shfl_sync(FULLM, a0, k);
            a0 = (lane > k) ? fmaf(-r0[k], zk, a0) : a0;
            a1 = fmaf(-r1[k], zk, a1);
        } else {
            float zk = __shfl_sync(FULLM, a1, k - 32);
            a1 = (lane > k - 32) ? fmaf(-r1[k], zk, a1) : a1;
        }
    }
#pragma unroll
    for (int k = 63; k >= 0; --k) {
        if (k >= 32) {
            float xk = __shfl_sync(FULLM, a1 * dinv1, k - 32);
            x1 = (lane == k - 32) ? xk : x1;
            a1 = (lane < k - 32) ? fmaf(-r1[k], xk, a1) : a1;
            a0 = fmaf(-r0[k], xk, a0);
        } else {
            float xk = __shfl_sync(FULLM, a0 * dinv0, k);
            x0 = (lane == k) ? xk : x0;
            a0 = (lane < k) ? fmaf(-r0[k], xk, a0) : a0;
        }
    }
}

// Solve Q^T x = f with COLUMN-distributed factors:
//   c0[j] = LU(j, lane), c1[j] = LU(j, lane+32)
// Q^T = U^T L^T:  forward U^T z = f, backward L^T x = z.
__device__ __forceinline__ void solveT64(const float (&c0)[64], const float (&c1)[64],
                                         float dinv0, float dinv1, int lane,
                                         float f0, float f1, float& x0, float& x1)
{
    float a0 = f0, a1 = f1;
    // forward: U^T (lower tri, diag U(k,k)=1/dinv); U^T(t,k)=U(k,t)=c_t[k]
#pragma unroll
    for (int k = 0; k < 64; ++k) {
        if (k < 32) {
            float zk = __shfl_sync(FULLM, a0 * dinv0, k);
            a0 = (lane > k) ? fmaf(-c0[k], zk, a0) : a0;
            a1 = fmaf(-c1[k], zk, a1);
        } else {
            float zk = __shfl_sync(FULLM, a1 * dinv1, k - 32);
            a1 = (lane > k - 32) ? fmaf(-c1[k], zk, a1) : a1;
        }
    }
    float z0 = a0 * dinv0;
    float z1 = a1 * dinv1;
    // backward: L^T (unit upper); L^T(t,j)=L(j,t)=c_t[j], j>t
    a0 = z0; a1 = z1;
#pragma unroll
    for (int j = 63; j >= 0; --j) {
        if (j >= 32) {
            float xj = __shfl_sync(FULLM, a1, j - 32);
            x1 = (lane == j - 32) ? xj : x1;
            a1 = (lane < j - 32) ? fmaf(-c1[j], xj, a1) : a1;
            a0 = fmaf(-c0[j], xj, a0);
        } else {
            float xj = __shfl_sync(FULLM, a0, j);
            x0 = (lane == j) ? xj : x0;
            a0 = (lane < j) ? fmaf(-c0[j], xj, a0) : a0;
        }
    }
}

// y = W x with Wt pre-transposed: y_i = sum_j Wt[j*64+i] * x_j
__device__ __forceinline__ void matvec64(const float* __restrict__ Wt, int lane,
                                         float x0, float x1, float& y0, float& y1)
{
    float a0 = 0.0f, a1 = 0.0f;
#pragma unroll
    for (int j = 0; j < 64; ++j) {
        float xj = (j < 32) ? __shfl_sync(FULLM, x0, j)
                            : __shfl_sync(FULLM, x1, j - 32);
        a0 = fmaf(Wt[j * 64 + lane],      xj, a0);
        a1 = fmaf(Wt[j * 64 + lane + 32], xj, a1);
    }
    y0 = a0; y1 = a1;
}

// ---------------------------------------------------------------------------
// Kernel 2: warp-per-sample. LUT-based expand -> smem A, ONE register LU of
// Q = I + A, then:
//   mis    = 2 Q^{-1} li  - li
//   latent = 2 Q^{-T} fc2 - fc2       (B = I - A = Q^T)
// Transposed factors obtained via smem round-trip through the dead sA tile.
// ---------------------------------------------------------------------------
__global__ __launch_bounds__(64) void k_warp(
    const float* __restrict__ li,
    const float* __restrict__ b1v, const float* __restrict__ b2v,
    const float* __restrict__ b3v, const float* __restrict__ b4v,
    const float* __restrict__ b5v,
    const float* __restrict__ W6,  const float* __restrict__ b6v,
    float* __restrict__ out)
{
    __shared__ float sAall[2 * 64 * LDF];

    const int lane = threadIdx.x & 31;
    const int wid  = threadIdx.x >> 5;
    const int n    = blockIdx.x * 2 + wid;
    float* sA = sAall + wid * 64 * LDF;

    // ---- Expand packed vec into skew matrix A (LUT offsets; 63*32 == 2016)
    const float* __restrict__ vec = g_vec + (size_t)n * GD;
#pragma unroll
    for (int i = 0; i < 63; ++i) {
        int p = lane + i * 32;
        float v = vec[p];
        unsigned int e = g_rc[p];
        sA[e & 0xffffu] = -v;     // A[r][c] = -vec (r>c)
        sA[e >> 16]     =  v;     // A[c][r] = +vec
    }
    __syncwarp();

    // ---- Build Q = I + A rows (conflict-free LDS)
    float r0[64], r1[64];
    float dinv0 = 1.0f, dinv1 = 1.0f;
#pragma unroll
    for (int j = 0; j < 64; ++j) {
        r0[j] = (j == lane)      ? 1.0f : sA[lane * LDF + j];
        r1[j] = (j == lane + 32) ? 1.0f : sA[(lane + 32) * LDF + j];
    }

    lu64(r0, r1, dinv0, dinv1, lane);

    // ---- mis = 2 Q^{-1} li - li
    float li0 = li[n * 64 + lane];
    float li1 = li[n * 64 + lane + 32];
    float u0 = 0.0f, u1 = 0.0f;
    solve64(r0, r1, dinv0, dinv1, lane, li0, li1, u0, u1);
    float m0 = 2.0f * u0 - li0;
    float m1 = 2.0f * u1 - li1;

    // ---- MLP core
    float h0, h1;
    matvec64(g_Wt + 0 * 4096, lane, m0, m1, h0, h1);
    h0 = fmaxf(h0 + b1v[lane], 0.0f);
    h1 = fmaxf(h1 + b1v[lane + 32], 0.0f);
    float f0, f1;
    matvec64(g_Wt + 1 * 4096, lane, h0, h1, f0, f1);
    f0 += b2v[lane];
    f1 += b2v[lane + 32];

    // ---- Transpose LU factors via smem round-trip (sA is dead now)
    __syncwarp();
#pragma unroll
    for (int j = 0; j < 64; ++j) {
        sA[lane * LDF + j]        = r0[j];
        sA[(lane + 32) * LDF + j] = r1[j];
    }
    __syncwarp();
#pragma unroll
    for (int j = 0; j < 64; ++j) {
        r0[j] = sA[j * LDF + lane];        // column lane
        r1[j] = sA[j * LDF + lane + 32];   // column lane+32
    }

    // ---- latent = 2 Q^{-T} fc2 - fc2   (B = Q^T)
    float v0 = 0.0f, v1 = 0.0f;
    solveT64(r0, r1, dinv0, dinv1, lane, f0, f1, v0, v1);
    float L0 = 2.0f * v0 - f0;
    float L1 = 2.0f * v1 - f1;
    out[LAT_OFF + n * 64 + lane]      = L0;
    out[LAT_OFF + n * 64 + lane + 32] = L1;

    // ---- recons = W4 relu(W3 latent + b3) + b4
    float t30, t31;
    matvec64(g_Wt + 2 * 4096, lane, L0, L1, t30, t31);
    t30 = fmaxf(t30 + b3v[lane], 0.0f);
    t31 = fmaxf(t31 + b3v[lane + 32], 0.0f);
    float rc0, rc1;
    matvec64(g_Wt + 3 * 4096, lane, t30, t31, rc0, rc1);
    out[REC_OFF + n * 64 + lane]      = rc0 + b4v[lane];
    out[REC_OFF + n * 64 + lane + 32] = rc1 + b4v[lane + 32];

    // ---- pred = W6 relu(W5 latent + b5) + b6
    float t50, t51;
    matvec64(g_Wt + 4 * 4096, lane, L0, L1, t50, t51);
    t50 = fmaxf(t50 + b5v[lane], 0.0f);
    t51 = fmaxf(t51 + b5v[lane + 32], 0.0f);
    float p0 = W6[lane] * t50      + W6[32 + lane] * t51;
    float p1 = W6[64 + lane] * t50 + W6[96 + lane] * t51;
#pragma unroll
    for (int off = 16; off; off >>= 1) {
        p0 += __shfl_xor_sync(FULLM, p0, off);
        p1 += __shfl_xor_sync(FULLM, p1, off);
    }
    if (lane == 0) {
        out[PRED_OFF + n * 2]     = p0 + b6v[0];
        out[PRED_OFF + n * 2 + 1] = p1 + b6v[1];
    }
}

// ---------------------------------------------------------------------------
extern "C" void kernel_launch(void* const* d_in, const int* in_sizes, int n_in,
                              void* d_out, int out_size)
{
    const float* li  = (const float*)d_in[0];
    const float* gi  = (const float*)d_in[1];
    const float* Wup = (const float*)d_in[2];
    const float* bup = (const float*)d_in[3];
    const float* W1  = (const float*)d_in[4];
    const float* b1  = (const float*)d_in[5];
    const float* W2  = (const float*)d_in[6];
    const float* b2  = (const float*)d_in[7];
    const float* W3  = (const float*)d_in[8];
    const float* b3  = (const float*)d_in[9];
    const float* W4  = (const float*)d_in[10];
    const float* b4  = (const float*)d_in[11];
    const float* W5  = (const float*)d_in[12];
    const float* b5  = (const float*)d_in[13];
    const float* W6  = (const float*)d_in[14];
    const float* b6  = (const float*)d_in[15];
    float* out = (float*)d_out;

    k_prep<<<88, 256>>>(W1, W2, W3, W4, W5);
    dim3 g1(32, 64);
    k_buildA<<<g1, 256>>>(gi, Wup, bup);
    k_warp<<<NSAMP / 2, 64>>>(li, b1, b2, b3, b4, b5, W6, b6, out);
}